// round 5
// baseline (speedup 1.0000x reference)
#include <cuda_runtime.h>

#define N_NODES 50000
#define N_EDGES 800000
#define N_TOT_EDGES (N_EDGES + N_NODES)   // self-loops appended

// ------------------------- scratch (device globals; no allocs allowed) ------
__device__ float g_hf [(size_t)N_NODES * 512];   // per-layer GEMM output h
__device__ float g_buf[(size_t)N_NODES * 512];   // layer activation ping-pong
__device__ float g_agg[(size_t)N_NODES * 512];   // segment-sum accumulator
__device__ float g_as [N_NODES * 4];
__device__ float g_ad [N_NODES * 4];
__device__ float g_m  [N_NODES * 4];
__device__ float g_z  [N_NODES * 4];

// ------------------------- helpers -----------------------------------------
__device__ __forceinline__ void atomicMaxFloat(float* addr, float val) {
    // valid given init to -inf bit pattern
    if (val >= 0.0f) atomicMax((int*)addr, __float_as_int(val));
    else             atomicMin((unsigned int*)addr, __float_as_uint(val));
}

// ------------------------- SGEMM: C = A[M,K] * W[Nout,K]^T (+bias, relu) ----
#define BM 128
#define BN 128
#define BK 8
__global__ __launch_bounds__(256) void sgemm_nt(
    const float* __restrict__ A, const float* __restrict__ W,
    float* __restrict__ C, const float* __restrict__ bias,
    int M, int Nout, int K, int relu)
{
    __shared__ float As[BK][BM];
    __shared__ float Bs[BK][BN];
    const int tid  = threadIdx.x;
    const int trow = tid / 16;            // 0..15
    const int tcol = tid % 16;            // 0..15
    const int aBase = blockIdx.y * BM;
    const int bBase = blockIdx.x * BN;

    const int lrow = tid >> 1;            // 0..127
    const int lk   = (tid & 1) * 4;       // 0 or 4

    float acc[8][8];
    #pragma unroll
    for (int i = 0; i < 8; i++)
        #pragma unroll
        for (int j = 0; j < 8; j++) acc[i][j] = 0.0f;

    for (int k0 = 0; k0 < K; k0 += BK) {
        int arow = aBase + lrow;
        float4 av = make_float4(0.f, 0.f, 0.f, 0.f);
        if (arow < M) av = *(const float4*)(A + (size_t)arow * K + k0 + lk);
        As[lk+0][lrow] = av.x; As[lk+1][lrow] = av.y;
        As[lk+2][lrow] = av.z; As[lk+3][lrow] = av.w;
        float4 bv = *(const float4*)(W + (size_t)(bBase + lrow) * K + k0 + lk);
        Bs[lk+0][lrow] = bv.x; Bs[lk+1][lrow] = bv.y;
        Bs[lk+2][lrow] = bv.z; Bs[lk+3][lrow] = bv.w;
        __syncthreads();
        #pragma unroll
        for (int kk = 0; kk < BK; kk++) {
            float af[8], bf[8];
            #pragma unroll
            for (int i = 0; i < 8; i++) af[i] = As[kk][trow*8 + i];
            #pragma unroll
            for (int j = 0; j < 8; j++) bf[j] = Bs[kk][tcol*8 + j];
            #pragma unroll
            for (int i = 0; i < 8; i++)
                #pragma unroll
                for (int j = 0; j < 8; j++)
                    acc[i][j] += af[i] * bf[j];
        }
        __syncthreads();
    }
    #pragma unroll
    for (int i = 0; i < 8; i++) {
        int row = aBase + trow*8 + i;
        if (row >= M) continue;
        #pragma unroll
        for (int j = 0; j < 8; j++) {
            int col = bBase + tcol*8 + j;
            float v = acc[i][j];
            if (bias) v += bias[col];
            if (relu) v = fmaxf(v, 0.0f);
            C[(size_t)row * Nout + col] = v;
        }
    }
}

// ------------------------- per-node attention logits ------------------------
// one warp per (node, head): alpha_s = <h[n,h,:], a_src[h,:]>, same for a_dst
__global__ void compute_alphas(const float* __restrict__ hf,
    const float* __restrict__ a_src, const float* __restrict__ a_dst,
    float* __restrict__ as_, float* __restrict__ ad_, int H)
{
    int n    = blockIdx.x;
    int head = threadIdx.y;
    int lane = threadIdx.x;
    const float* hp = hf + ((size_t)n * H + head) * 128;
    float s1 = 0.f, s2 = 0.f;
    #pragma unroll
    for (int c = lane; c < 128; c += 32) {
        float hv = hp[c];
        s1 += hv * a_src[head*128 + c];
        s2 += hv * a_dst[head*128 + c];
    }
    #pragma unroll
    for (int o = 16; o > 0; o >>= 1) {
        s1 += __shfl_down_sync(0xffffffffu, s1, o);
        s2 += __shfl_down_sync(0xffffffffu, s2, o);
    }
    if (lane == 0) { as_[n*H + head] = s1; ad_[n*H + head] = s2; }
}

__global__ void init_mz(float* __restrict__ m, float* __restrict__ z, int n) {
    int i = blockIdx.x * blockDim.x + threadIdx.x;
    if (i < n) { m[i] = __int_as_float(0xff800000u); z[i] = 0.f; }
}

// ------------------------- edge passes --------------------------------------
__global__ void edge_max(const int* __restrict__ ei, int H,
    const float* __restrict__ as_, const float* __restrict__ ad_,
    float* __restrict__ m)
{
    int t = blockIdx.x * blockDim.x + threadIdx.x;
    int total = N_TOT_EDGES * H;
    if (t >= total) return;
    int h = t % H, e = t / H;
    int s, d;
    if (e < N_EDGES) { s = ei[e]; d = ei[N_EDGES + e]; } else { s = d = e - N_EDGES; }
    float v = as_[s*H + h] + ad_[d*H + h];
    v = v > 0.f ? v : 0.2f * v;
    atomicMaxFloat(&m[d*H + h], v);
}

__global__ void edge_sum(const int* __restrict__ ei, int H,
    const float* __restrict__ as_, const float* __restrict__ ad_,
    const float* __restrict__ m, float* __restrict__ z)
{
    int t = blockIdx.x * blockDim.x + threadIdx.x;
    int total = N_TOT_EDGES * H;
    if (t >= total) return;
    int h = t % H, e = t / H;
    int s, d;
    if (e < N_EDGES) { s = ei[e]; d = ei[N_EDGES + e]; } else { s = d = e - N_EDGES; }
    float v = as_[s*H + h] + ad_[d*H + h];
    v = v > 0.f ? v : 0.2f * v;
    atomicAdd(&z[d*H + h], expf(v - m[d*H + h]));
}

// one warp per (edge, head): gather 128 ch of h[src], scale, vectorized
// reduction into agg[dst]. Normalization by z folded into the node epilogue.
__global__ void edge_agg(const int* __restrict__ ei, int H,
    const float* __restrict__ as_, const float* __restrict__ ad_,
    const float* __restrict__ m, const float* __restrict__ hf,
    float* __restrict__ agg)
{
    int gw   = (blockIdx.x * blockDim.x + threadIdx.x) >> 5;
    int lane = threadIdx.x & 31;
    int total = N_TOT_EDGES * H;
    if (gw >= total) return;
    int h = gw % H, e = gw / H;
    int s, d;
    if (e < N_EDGES) { s = ei[e]; d = ei[N_EDGES + e]; } else { s = d = e - N_EDGES; }
    float v = as_[s*H + h] + ad_[d*H + h];
    v = v > 0.f ? v : 0.2f * v;
    float alpha = expf(v - m[d*H + h]);

    const float4 hx = *(const float4*)(hf + (((size_t)s*H + h) << 7) + lane*4);
    float* dstp = agg + (((size_t)d*H + h) << 7) + lane*4;
    asm volatile("red.global.add.v4.f32 [%0], {%1, %2, %3, %4};"
        :: "l"(dstp), "f"(hx.x*alpha), "f"(hx.y*alpha), "f"(hx.z*alpha), "f"(hx.w*alpha)
        : "memory");
}

// ------------------------- node epilogue: out = agg/(z+eps) + b (, relu) ----
__global__ void normalize_out(const float* __restrict__ agg,
    const float* __restrict__ z, const float* __restrict__ bias,
    float* __restrict__ out, int H, int relu)
{
    int idx = blockIdx.x * blockDim.x + threadIdx.x;
    int total = N_NODES * H * 128;
    if (idx >= total) return;
    int n  = idx / (H * 128);
    int hc = idx - n * H * 128;
    int head = hc >> 7;
    float v = agg[idx] / (z[n*H + head] + 1e-16f) + bias[hc];
    if (relu) v = fmaxf(v, 0.f);
    out[idx] = v;
}

// ------------------------- host orchestration -------------------------------
static void run_gat_layer(const float* xin, int K, const float* Wl,
    const float* a_src, const float* a_dst, const float* b, int H,
    const int* ei, float* hf, float* agg, float* as_, float* ad_,
    float* m, float* z, float* out, int relu)
{
    int Nout = H * 128;
    dim3 ggrid(Nout / BN, (N_NODES + BM - 1) / BM);
    sgemm_nt<<<ggrid, 256>>>(xin, Wl, hf, nullptr, N_NODES, Nout, K, 0);
    compute_alphas<<<N_NODES, dim3(32, H)>>>(hf, a_src, a_dst, as_, ad_, H);
    int nmz = N_NODES * H;
    init_mz<<<(nmz + 255)/256, 256>>>(m, z, nmz);
    cudaMemsetAsync(agg, 0, (size_t)N_NODES * Nout * sizeof(float));
    int tot = N_TOT_EDGES * H;
    edge_max<<<(tot + 255)/256, 256>>>(ei, H, as_, ad_, m);
    edge_sum<<<(tot + 255)/256, 256>>>(ei, H, as_, ad_, m, z);
    long long warps = (long long)tot * 32;
    edge_agg<<<(unsigned)((warps + 255)/256), 256>>>(ei, H, as_, ad_, m, hf, agg);
    normalize_out<<<(N_NODES*Nout + 255)/256, 256>>>(agg, z, b, out, H, relu);
}

extern "C" void kernel_launch(void* const* d_in, const int* in_sizes, int n_in,
                              void* d_out, int out_size)
{
    const float* x   = (const float*)d_in[0];
    const int*   ei  = (const int*)  d_in[1];
    const float* W0  = (const float*)d_in[2];
    const float* as0 = (const float*)d_in[3];
    const float* ad0 = (const float*)d_in[4];
    const float* b0  = (const float*)d_in[5];
    const float* W1  = (const float*)d_in[6];
    const float* as1 = (const float*)d_in[7];
    const float* ad1 = (const float*)d_in[8];
    const float* b1  = (const float*)d_in[9];
    const float* W2  = (const float*)d_in[10];
    const float* as2 = (const float*)d_in[11];
    const float* ad2 = (const float*)d_in[12];
    const float* b2  = (const float*)d_in[13];
    const float* Wv  = (const float*)d_in[14];
    const float* bv  = (const float*)d_in[15];
    const float* Wt  = (const float*)d_in[16];
    const float* bt  = (const float*)d_in[17];

    float *hf, *buf, *agg, *as_, *ad_, *m, *z;
    cudaGetSymbolAddress((void**)&hf,  g_hf);
    cudaGetSymbolAddress((void**)&buf, g_buf);
    cudaGetSymbolAddress((void**)&agg, g_agg);
    cudaGetSymbolAddress((void**)&as_, g_as);
    cudaGetSymbolAddress((void**)&ad_, g_ad);
    cudaGetSymbolAddress((void**)&m,   g_m);
    cudaGetSymbolAddress((void**)&z,   g_z);

    float* out = (float*)d_out;
    float* h2  = out;                               // [N,128]
    float* xv  = out + (size_t)N_NODES * 128;       // [N,128]
    float* xt  = out + (size_t)N_NODES * 256;       // [N,128]

    // layer 0: 512 -> 4x128, relu
    run_gat_layer(x,   512, W0, as0, ad0, b0, 4, ei, hf, agg, as_, ad_, m, z, buf, 1);
    // layer 1: 512 -> 4x128, relu (in-place ping-pong on buf is stream-safe)
    run_gat_layer(buf, 512, W1, as1, ad1, b1, 4, ei, hf, agg, as_, ad_, m, z, buf, 1);
    // layer 2: 512 -> 1x128, no relu, writes h directly into d_out
    run_gat_layer(buf, 512, W2, as2, ad2, b2, 1, ei, hf, agg, as_, ad_, m, z, h2, 0);

    // output heads
    dim3 hgrid(1, (N_NODES + BM - 1) / BM);
    sgemm_nt<<<hgrid, 256>>>(h2, Wv, xv, bv, N_NODES, 128, 128, 1);
    sgemm_nt<<<hgrid, 256>>>(h2, Wt, xt, bt, N_NODES, 128, 128, 1);
}

// round 6
// speedup vs baseline: 1.2434x; 1.2434x over previous
#include <cuda_runtime.h>
#include <cstdint>

#define N_NODES 50000
#define N_EDGES 800000
#define N_TOT_EDGES (N_EDGES + N_NODES)   // self-loops appended

// ------------------------- scratch (device globals; no allocs allowed) ------
__device__ float g_hf [(size_t)N_NODES * 512];   // per-layer GEMM output h
__device__ float g_buf[(size_t)N_NODES * 512];   // layer activation ping-pong
__device__ float g_agg[(size_t)N_NODES * 512];   // segment-sum accumulator
__device__ float g_as [N_NODES * 4];
__device__ float g_ad [N_NODES * 4];
__device__ float g_m  [N_NODES * 4];
__device__ float g_z  [N_NODES * 4];

// ------------------------- helpers -----------------------------------------
__device__ __forceinline__ void atomicMaxFloat(float* addr, float val) {
    if (val >= 0.0f) atomicMax((int*)addr, __float_as_int(val));
    else             atomicMin((unsigned int*)addr, __float_as_uint(val));
}

// =============================================================================
// Tensor-core GEMM: C[M,Nout] = A[M,K] * W[Nout,K]^T (+bias, relu)
// tf32 mma.sync m16n8k8 with 2-term precision split (Ahi*Bhi + Alo*Bhi + Ahi*Blo)
// => fp32-equivalent accuracy at ~273 TF/s tf32 pipe instead of ~68 TF/s FFMA.
// CTA: 128x128 tile, 256 threads = 8 warps of 64x32; K chunked by 32.
// Requires: K % 32 == 0, Nout % 128 == 0 (true for all call sites here).
// =============================================================================
#define BM 128
#define BN 128
#define BKC 32
#define SLD 36                       // smem row stride (floats), pad for banks
#define GEMM_SMEM_BYTES (4 * 128 * SLD * 4)

__device__ __forceinline__ void mma8(float* d, const unsigned* a, const unsigned* b) {
    asm volatile(
        "mma.sync.aligned.m16n8k8.row.col.f32.tf32.tf32.f32 "
        "{%0,%1,%2,%3}, {%4,%5,%6,%7}, {%8,%9}, {%0,%1,%2,%3};"
        : "+f"(d[0]), "+f"(d[1]), "+f"(d[2]), "+f"(d[3])
        : "r"(a[0]), "r"(a[1]), "r"(a[2]), "r"(a[3]), "r"(b[0]), "r"(b[1]));
}

__device__ __forceinline__ void split_hi_lo(float v, float& hi, float& lo) {
    hi = __uint_as_float(__float_as_uint(v) & 0xFFFFE000u);  // exact tf32
    lo = v - hi;                                             // exact residual
}

__global__ __launch_bounds__(256) void mma_gemm_nt(
    const float* __restrict__ A, const float* __restrict__ W,
    float* __restrict__ C, const float* __restrict__ bias,
    int M, int Nout, int K, int relu)
{
    extern __shared__ float sm[];
    float* Ahi = sm;
    float* Alo = sm + 128 * SLD;
    float* Bhi = sm + 2 * 128 * SLD;
    float* Blo = sm + 3 * 128 * SLD;

    const int tid  = threadIdx.x;
    const int lane = tid & 31;
    const int wid  = tid >> 5;
    const int g    = lane >> 2;      // groupID 0..7
    const int t    = lane & 3;       // threadID-in-group 0..3
    const int wm   = (wid & 1) * 64; // warp M offset in tile
    const int wn   = (wid >> 1) * 32;// warp N offset in tile
    const int mBase = blockIdx.y * BM;
    const int nBase = blockIdx.x * BN;

    // global->smem loader mapping: 32 rows x 8 float4 per pass, 4 passes
    const int lr = tid >> 3;         // 0..31
    const int lc = (tid & 7) * 4;    // 0,4,...,28

    float acc[4][4][4];
    #pragma unroll
    for (int mt = 0; mt < 4; mt++)
        #pragma unroll
        for (int nt = 0; nt < 4; nt++)
            #pragma unroll
            for (int i = 0; i < 4; i++) acc[mt][nt][i] = 0.0f;

    for (int k0 = 0; k0 < K; k0 += BKC) {
        #pragma unroll
        for (int i = 0; i < 4; i++) {
            int r = lr + i * 32;
            // ---- A tile (row-guarded) ----
            int arow = mBase + r;
            float4 av = make_float4(0.f, 0.f, 0.f, 0.f);
            if (arow < M) av = *(const float4*)(A + (size_t)arow * K + k0 + lc);
            float4 ah, al;
            split_hi_lo(av.x, ah.x, al.x); split_hi_lo(av.y, ah.y, al.y);
            split_hi_lo(av.z, ah.z, al.z); split_hi_lo(av.w, ah.w, al.w);
            *(float4*)(Ahi + r * SLD + lc) = ah;
            *(float4*)(Alo + r * SLD + lc) = al;
            // ---- B tile (always in-bounds: Nout % 128 == 0) ----
            float4 bv = *(const float4*)(W + (size_t)(nBase + r) * K + k0 + lc);
            float4 bh, bl;
            split_hi_lo(bv.x, bh.x, bl.x); split_hi_lo(bv.y, bh.y, bl.y);
            split_hi_lo(bv.z, bh.z, bl.z); split_hi_lo(bv.w, bh.w, bl.w);
            *(float4*)(Bhi + r * SLD + lc) = bh;
            *(float4*)(Blo + r * SLD + lc) = bl;
        }
        __syncthreads();

        #pragma unroll
        for (int kk = 0; kk < 4; kk++) {
            const int kb = kk * 8;
            unsigned ah[4][4], al[4][4], bh[4][2], bl[4][2];
            #pragma unroll
            for (int mt = 0; mt < 4; mt++) {
                const float* p = Ahi + (wm + mt * 16 + g) * SLD + kb + t;
                ah[mt][0] = __float_as_uint(p[0]);
                ah[mt][1] = __float_as_uint(p[8 * SLD]);
                ah[mt][2] = __float_as_uint(p[4]);
                ah[mt][3] = __float_as_uint(p[8 * SLD + 4]);
                const float* q = Alo + (wm + mt * 16 + g) * SLD + kb + t;
                al[mt][0] = __float_as_uint(q[0]);
                al[mt][1] = __float_as_uint(q[8 * SLD]);
                al[mt][2] = __float_as_uint(q[4]);
                al[mt][3] = __float_as_uint(q[8 * SLD + 4]);
            }
            #pragma unroll
            for (int nt = 0; nt < 4; nt++) {
                const float* p = Bhi + (wn + nt * 8 + g) * SLD + kb + t;
                bh[nt][0] = __float_as_uint(p[0]);
                bh[nt][1] = __float_as_uint(p[4]);
                const float* q = Blo + (wn + nt * 8 + g) * SLD + kb + t;
                bl[nt][0] = __float_as_uint(q[0]);
                bl[nt][1] = __float_as_uint(q[4]);
            }
            #pragma unroll
            for (int mt = 0; mt < 4; mt++)
                #pragma unroll
                for (int nt = 0; nt < 4; nt++) {
                    mma8(acc[mt][nt], ah[mt], bh[nt]);  // hi*hi
                    mma8(acc[mt][nt], al[mt], bh[nt]);  // lo*hi
                    mma8(acc[mt][nt], ah[mt], bl[nt]);  // hi*lo
                }
        }
        __syncthreads();
    }

    // ---- epilogue ----
    #pragma unroll
    for (int mt = 0; mt < 4; mt++) {
        int row0 = mBase + wm + mt * 16 + g;
        #pragma unroll
        for (int nt = 0; nt < 4; nt++) {
            int col = nBase + wn + nt * 8 + 2 * t;
            float b0 = bias ? bias[col]     : 0.f;
            float b1 = bias ? bias[col + 1] : 0.f;
            if (row0 < M) {
                float v0 = acc[mt][nt][0] + b0;
                float v1 = acc[mt][nt][1] + b1;
                if (relu) { v0 = fmaxf(v0, 0.f); v1 = fmaxf(v1, 0.f); }
                C[(size_t)row0 * Nout + col]     = v0;
                C[(size_t)row0 * Nout + col + 1] = v1;
            }
            if (row0 + 8 < M) {
                float v2 = acc[mt][nt][2] + b0;
                float v3 = acc[mt][nt][3] + b1;
                if (relu) { v2 = fmaxf(v2, 0.f); v3 = fmaxf(v3, 0.f); }
                C[(size_t)(row0 + 8) * Nout + col]     = v2;
                C[(size_t)(row0 + 8) * Nout + col + 1] = v3;
            }
        }
    }
}

// ------------------------- per-node attention logits ------------------------
__global__ void compute_alphas(const float* __restrict__ hf,
    const float* __restrict__ a_src, const float* __restrict__ a_dst,
    float* __restrict__ as_, float* __restrict__ ad_, int H)
{
    int n    = blockIdx.x;
    int head = threadIdx.y;
    int lane = threadIdx.x;
    const float* hp = hf + ((size_t)n * H + head) * 128;
    float s1 = 0.f, s2 = 0.f;
    #pragma unroll
    for (int c = lane; c < 128; c += 32) {
        float hv = hp[c];
        s1 += hv * a_src[head*128 + c];
        s2 += hv * a_dst[head*128 + c];
    }
    #pragma unroll
    for (int o = 16; o > 0; o >>= 1) {
        s1 += __shfl_down_sync(0xffffffffu, s1, o);
        s2 += __shfl_down_sync(0xffffffffu, s2, o);
    }
    if (lane == 0) { as_[n*H + head] = s1; ad_[n*H + head] = s2; }
}

__global__ void init_mz(float* __restrict__ m, float* __restrict__ z, int n) {
    int i = blockIdx.x * blockDim.x + threadIdx.x;
    if (i < n) { m[i] = __int_as_float(0xff800000u); z[i] = 0.f; }
}

// ------------------------- edge passes --------------------------------------
__global__ void edge_max(const int* __restrict__ ei, int H,
    const float* __restrict__ as_, const float* __restrict__ ad_,
    float* __restrict__ m)
{
    int t = blockIdx.x * blockDim.x + threadIdx.x;
    int total = N_TOT_EDGES * H;
    if (t >= total) return;
    int h = t % H, e = t / H;
    int s, d;
    if (e < N_EDGES) { s = ei[e]; d = ei[N_EDGES + e]; } else { s = d = e - N_EDGES; }
    float v = as_[s*H + h] + ad_[d*H + h];
    v = v > 0.f ? v : 0.2f * v;
    atomicMaxFloat(&m[d*H + h], v);
}

__global__ void edge_sum(const int* __restrict__ ei, int H,
    const float* __restrict__ as_, const float* __restrict__ ad_,
    const float* __restrict__ m, float* __restrict__ z)
{
    int t = blockIdx.x * blockDim.x + threadIdx.x;
    int total = N_TOT_EDGES * H;
    if (t >= total) return;
    int h = t % H, e = t / H;
    int s, d;
    if (e < N_EDGES) { s = ei[e]; d = ei[N_EDGES + e]; } else { s = d = e - N_EDGES; }
    float v = as_[s*H + h] + ad_[d*H + h];
    v = v > 0.f ? v : 0.2f * v;
    atomicAdd(&z[d*H + h], expf(v - m[d*H + h]));
}

__global__ void edge_agg(const int* __restrict__ ei, int H,
    const float* __restrict__ as_, const float* __restrict__ ad_,
    const float* __restrict__ m, const float* __restrict__ hf,
    float* __restrict__ agg)
{
    int gw   = (blockIdx.x * blockDim.x + threadIdx.x) >> 5;
    int lane = threadIdx.x & 31;
    int total = N_TOT_EDGES * H;
    if (gw >= total) return;
    int h = gw % H, e = gw / H;
    int s, d;
    if (e < N_EDGES) { s = ei[e]; d = ei[N_EDGES + e]; } else { s = d = e - N_EDGES; }
    float v = as_[s*H + h] + ad_[d*H + h];
    v = v > 0.f ? v : 0.2f * v;
    float alpha = expf(v - m[d*H + h]);

    const float4 hx = *(const float4*)(hf + (((size_t)s*H + h) << 7) + lane*4);
    float* dstp = agg + (((size_t)d*H + h) << 7) + lane*4;
    asm volatile("red.global.add.v4.f32 [%0], {%1, %2, %3, %4};"
        :: "l"(dstp), "f"(hx.x*alpha), "f"(hx.y*alpha), "f"(hx.z*alpha), "f"(hx.w*alpha)
        : "memory");
}

// ------------------------- node epilogue ------------------------------------
__global__ void normalize_out(const float* __restrict__ agg,
    const float* __restrict__ z, const float* __restrict__ bias,
    float* __restrict__ out, int H, int relu)
{
    int idx = blockIdx.x * blockDim.x + threadIdx.x;
    int total = N_NODES * H * 128;
    if (idx >= total) return;
    int n  = idx / (H * 128);
    int hc = idx - n * H * 128;
    int head = hc >> 7;
    float v = agg[idx] / (z[n*H + head] + 1e-16f) + bias[hc];
    if (relu) v = fmaxf(v, 0.f);
    out[idx] = v;
}

// ------------------------- host orchestration -------------------------------
static void launch_gemm(const float* A, const float* W, float* C,
                        const float* bias, int M, int Nout, int K, int relu)
{
    dim3 grid(Nout / BN, (M + BM - 1) / BM);
    mma_gemm_nt<<<grid, 256, GEMM_SMEM_BYTES>>>(A, W, C, bias, M, Nout, K, relu);
}

static void run_gat_layer(const float* xin, int K, const float* Wl,
    const float* a_src, const float* a_dst, const float* b, int H,
    const int* ei, float* hf, float* agg, float* as_, float* ad_,
    float* m, float* z, float* out, int relu)
{
    int Nout = H * 128;
    launch_gemm(xin, Wl, hf, nullptr, N_NODES, Nout, K, 0);
    compute_alphas<<<N_NODES, dim3(32, H)>>>(hf, a_src, a_dst, as_, ad_, H);
    int nmz = N_NODES * H;
    init_mz<<<(nmz + 255)/256, 256>>>(m, z, nmz);
    cudaMemsetAsync(agg, 0, (size_t)N_NODES * Nout * sizeof(float));
    int tot = N_TOT_EDGES * H;
    edge_max<<<(tot + 255)/256, 256>>>(ei, H, as_, ad_, m);
    edge_sum<<<(tot + 255)/256, 256>>>(ei, H, as_, ad_, m, z);
    long long warps = (long long)tot * 32;
    edge_agg<<<(unsigned)((warps + 255)/256), 256>>>(ei, H, as_, ad_, m, hf, agg);
    normalize_out<<<(N_NODES*Nout + 255)/256, 256>>>(agg, z, b, out, H, relu);
}

extern "C" void kernel_launch(void* const* d_in, const int* in_sizes, int n_in,
                              void* d_out, int out_size)
{
    const float* x   = (const float*)d_in[0];
    const int*   ei  = (const int*)  d_in[1];
    const float* W0  = (const float*)d_in[2];
    const float* as0 = (const float*)d_in[3];
    const float* ad0 = (const float*)d_in[4];
    const float* b0  = (const float*)d_in[5];
    const float* W1  = (const float*)d_in[6];
    const float* as1 = (const float*)d_in[7];
    const float* ad1 = (const float*)d_in[8];
    const float* b1  = (const float*)d_in[9];
    const float* W2  = (const float*)d_in[10];
    const float* as2 = (const float*)d_in[11];
    const float* ad2 = (const float*)d_in[12];
    const float* b2  = (const float*)d_in[13];
    const float* Wv  = (const float*)d_in[14];
    const float* bv  = (const float*)d_in[15];
    const float* Wt  = (const float*)d_in[16];
    const float* bt  = (const float*)d_in[17];

    // allow 72KB dynamic smem for the mma gemm (not a stream op; capture-safe)
    cudaFuncSetAttribute(mma_gemm_nt,
                         cudaFuncAttributeMaxDynamicSharedMemorySize,
                         GEMM_SMEM_BYTES);

    float *hf, *buf, *agg, *as_, *ad_, *m, *z;
    cudaGetSymbolAddress((void**)&hf,  g_hf);
    cudaGetSymbolAddress((void**)&buf, g_buf);
    cudaGetSymbolAddress((void**)&agg, g_agg);
    cudaGetSymbolAddress((void**)&as_, g_as);
    cudaGetSymbolAddress((void**)&ad_, g_ad);
    cudaGetSymbolAddress((void**)&m,   g_m);
    cudaGetSymbolAddress((void**)&z,   g_z);

    float* out = (float*)d_out;
    float* h2  = out;                               // [N,128]
    float* xv  = out + (size_t)N_NODES * 128;       // [N,128]
    float* xt  = out + (size_t)N_NODES * 256;       // [N,128]

    // layer 0: 512 -> 4x128, relu
    run_gat_layer(x,   512, W0, as0, ad0, b0, 4, ei, hf, agg, as_, ad_, m, z, buf, 1);
    // layer 1: 512 -> 4x128, relu
    run_gat_layer(buf, 512, W1, as1, ad1, b1, 4, ei, hf, agg, as_, ad_, m, z, buf, 1);
    // layer 2: 512 -> 1x128, no relu, writes h directly into d_out
    run_gat_layer(buf, 512, W2, as2, ad2, b2, 1, ei, hf, agg, as_, ad_, m, z, h2, 0);

    // output heads
    launch_gemm(h2, Wv, xv, bv, N_NODES, 128, 128, 1);
    launch_gemm(h2, Wt, xt, bt, N_NODES, 128, 128, 1);
}

// round 8
// speedup vs baseline: 1.3614x; 1.0949x over previous
#include <cuda_runtime.h>
#include <cstdint>

#define N_NODES 50000
#define N_EDGES 800000
#define N_TOT_EDGES (N_EDGES + N_NODES)   // self-loops appended

// ------------------------- scratch (device globals; no allocs allowed) ------
__device__ float g_hf [(size_t)N_NODES * 512];   // per-layer GEMM output h
__device__ float g_buf[(size_t)N_NODES * 512];   // layer activation ping-pong
__device__ float g_agg[(size_t)N_NODES * 512];   // segment-sum accumulator
__device__ float g_as [N_NODES * 4];
__device__ float g_ad [N_NODES * 4];
__device__ float g_m  [N_NODES * 4];
__device__ float g_z  [N_NODES * 4];

// ------------------------- helpers -----------------------------------------
__device__ __forceinline__ void atomicMaxFloat(float* addr, float val) {
    if (val >= 0.0f) atomicMax((int*)addr, __float_as_int(val));
    else             atomicMin((unsigned int*)addr, __float_as_uint(val));
}

// =============================================================================
// Tensor-core GEMM: C[M,Nout] = A[M,K] * W[Nout,K]^T (+bias, relu)
// tf32 mma.sync m16n8k8, 2-term split (hi*hi + lo*hi + hi*lo) for fp32 accuracy.
// 2-stage cp.async double buffer: smem holds RAW fp32 tiles; the tf32 hi/lo
// split happens at fragment-load time in registers, off the load critical path.
// CTA: 128x128 tile, 256 threads = 8 warps of 64x32; K chunked by 32.
// Requires: K % 32 == 0, Nout % 128 == 0 (true for all call sites here).
// =============================================================================
#define BM 128
#define BN 128
#define BKC 32
#define SLD 36                       // smem row stride (floats); (4g+t)%32 conflict-free
#define GEMM_SMEM_BYTES (4 * 128 * SLD * 4)   // A0,A1,B0,B1 = 72KB

__device__ __forceinline__ void mma8(float* d, const unsigned* a, const unsigned* b) {
    asm volatile(
        "mma.sync.aligned.m16n8k8.row.col.f32.tf32.tf32.f32 "
        "{%0,%1,%2,%3}, {%4,%5,%6,%7}, {%8,%9}, {%0,%1,%2,%3};"
        : "+f"(d[0]), "+f"(d[1]), "+f"(d[2]), "+f"(d[3])
        : "r"(a[0]), "r"(a[1]), "r"(a[2]), "r"(a[3]), "r"(b[0]), "r"(b[1]));
}

__device__ __forceinline__ void split_u(float v, unsigned& hi, unsigned& lo) {
    unsigned h = __float_as_uint(v) & 0xFFFFE000u;           // exact tf32 truncation
    hi = h;
    lo = __float_as_uint(v - __uint_as_float(h));            // exact residual
}

__device__ __forceinline__ void cp_async16(uint32_t saddr, const void* gptr, int src_bytes) {
    asm volatile("cp.async.cg.shared.global [%0], [%1], 16, %2;"
        :: "r"(saddr), "l"(gptr), "r"(src_bytes));
}

__global__ __launch_bounds__(256) void mma_gemm_nt(
    const float* __restrict__ A, const float* __restrict__ W,
    float* __restrict__ C, const float* __restrict__ bias,
    int M, int Nout, int K, int relu)
{
    extern __shared__ float sm[];
    // layout: A[2][128][SLD], B[2][128][SLD]
    float* Asm[2] = { sm,               sm + 128 * SLD };
    float* Bsm[2] = { sm + 2*128*SLD,   sm + 3*128*SLD };
    const uint32_t smem_u32 = (uint32_t)__cvta_generic_to_shared(sm);

    const int tid  = threadIdx.x;
    const int lane = tid & 31;
    const int wid  = tid >> 5;
    const int g    = lane >> 2;      // groupID 0..7
    const int t    = lane & 3;       // threadID-in-group 0..3
    const int wm   = (wid & 1) * 64; // warp M offset in tile
    const int wn   = (wid >> 1) * 32;// warp N offset in tile
    const int mBase = blockIdx.y * BM;
    const int nBase = blockIdx.x * BN;

    // loader mapping: 32 rows x 8 float4 per pass, 4 passes per tile
    const int lr = tid >> 3;         // 0..31
    const int lc = (tid & 7) * 4;    // 0,4,...,28

    float acc[4][4][4];
    #pragma unroll
    for (int mt = 0; mt < 4; mt++)
        #pragma unroll
        for (int nt = 0; nt < 4; nt++)
            #pragma unroll
            for (int i = 0; i < 4; i++) acc[mt][nt][i] = 0.0f;

    const int nk = K / BKC;

    // ---- issue loads for one K-chunk into buffer b ----
    auto issue_chunk = [&](int ck, int b) {
        const int k0 = ck * BKC;
        const uint32_t aOff = smem_u32 + (uint32_t)(b * 128 * SLD) * 4;
        const uint32_t bOff = smem_u32 + (uint32_t)((2 + b) * 128 * SLD) * 4;
        #pragma unroll
        for (int i = 0; i < 4; i++) {
            int r = lr + i * 32;
            int arow = mBase + r;
            int ok = arow < M;
            const float* ag = A + (size_t)(ok ? arow : 0) * K + k0 + lc;
            cp_async16(aOff + (uint32_t)(r * SLD + lc) * 4, ag, ok ? 16 : 0);
            const float* bg = W + (size_t)(nBase + r) * K + k0 + lc;
            cp_async16(bOff + (uint32_t)(r * SLD + lc) * 4, bg, 16);
        }
        asm volatile("cp.async.commit_group;");
    };

    issue_chunk(0, 0);

    for (int ck = 0; ck < nk; ck++) {
        const int cur = ck & 1;
        if (ck + 1 < nk) {
            issue_chunk(ck + 1, cur ^ 1);
            asm volatile("cp.async.wait_group 1;");
        } else {
            asm volatile("cp.async.wait_group 0;");
        }
        __syncthreads();

        const float* Ac = Asm[cur];
        const float* Bc = Bsm[cur];
        #pragma unroll
        for (int kk = 0; kk < 4; kk++) {
            const int kb = kk * 8;
            unsigned ah[4][4], al[4][4], bh[4][2], bl[4][2];
            #pragma unroll
            for (int mt = 0; mt < 4; mt++) {
                const float* p = Ac + (wm + mt * 16 + g) * SLD + kb + t;
                split_u(p[0],           ah[mt][0], al[mt][0]);
                split_u(p[8 * SLD],     ah[mt][1], al[mt][1]);
                split_u(p[4],           ah[mt][2], al[mt][2]);
                split_u(p[8 * SLD + 4], ah[mt][3], al[mt][3]);
            }
            #pragma unroll
            for (int nt = 0; nt < 4; nt++) {
                const float* p = Bc + (wn + nt * 8 + g) * SLD + kb + t;
                split_u(p[0], bh[nt][0], bl[nt][0]);
                split_u(p[4], bh[nt][1], bl[nt][1]);
            }
            #pragma unroll
            for (int mt = 0; mt < 4; mt++)
                #pragma unroll
                for (int nt = 0; nt < 4; nt++) {
                    mma8(acc[mt][nt], ah[mt], bh[nt]);  // hi*hi
                    mma8(acc[mt][nt], al[mt], bh[nt]);  // lo*hi
                    mma8(acc[mt][nt], ah[mt], bl[nt]);  // hi*lo
                }
        }
        __syncthreads();   // all warps done with buf[cur] before it is refilled
    }

    // ---- epilogue ----
    #pragma unroll
    for (int mt = 0; mt < 4; mt++) {
        int row0 = mBase + wm + mt * 16 + g;
        #pragma unroll
        for (int nt = 0; nt < 4; nt++) {
            int col = nBase + wn + nt * 8 + 2 * t;
            float b0 = bias ? bias[col]     : 0.f;
            float b1 = bias ? bias[col + 1] : 0.f;
            if (row0 < M) {
                float v0 = acc[mt][nt][0] + b0;
                float v1 = acc[mt][nt][1] + b1;
                if (relu) { v0 = fmaxf(v0, 0.f); v1 = fmaxf(v1, 0.f); }
                C[(size_t)row0 * Nout + col]     = v0;
                C[(size_t)row0 * Nout + col + 1] = v1;
            }
            if (row0 + 8 < M) {
                float v2 = acc[mt][nt][2] + b0;
                float v3 = acc[mt][nt][3] + b1;
                if (relu) { v2 = fmaxf(v2, 0.f); v3 = fmaxf(v3, 0.f); }
                C[(size_t)(row0 + 8) * Nout + col]     = v2;
                C[(size_t)(row0 + 8) * Nout + col + 1] = v3;
            }
        }
    }
}

// ------------------------- per-node attention logits ------------------------
__global__ void compute_alphas(const float* __restrict__ hf,
    const float* __restrict__ a_src, const float* __restrict__ a_dst,
    float* __restrict__ as_, float* __restrict__ ad_, int H)
{
    int n    = blockIdx.x;
    int head = threadIdx.y;
    int lane = threadIdx.x;
    const float* hp = hf + ((size_t)n * H + head) * 128;
    float s1 = 0.f, s2 = 0.f;
    #pragma unroll
    for (int c = lane; c < 128; c += 32) {
        float hv = hp[c];
        s1 += hv * a_src[head*128 + c];
        s2 += hv * a_dst[head*128 + c];
    }
    #pragma unroll
    for (int o = 16; o > 0; o >>= 1) {
        s1 += __shfl_down_sync(0xffffffffu, s1, o);
        s2 += __shfl_down_sync(0xffffffffu, s2, o);
    }
    if (lane == 0) { as_[n*H + head] = s1; ad_[n*H + head] = s2; }
}

__global__ void init_mz(float* __restrict__ m, float* __restrict__ z, int n) {
    int i = blockIdx.x * blockDim.x + threadIdx.x;
    if (i < n) { m[i] = __int_as_float(0xff800000u); z[i] = 0.f; }
}

// ------------------------- edge passes --------------------------------------
__global__ void edge_max(const int* __restrict__ ei, int H,
    const float* __restrict__ as_, const float* __restrict__ ad_,
    float* __restrict__ m)
{
    int t = blockIdx.x * blockDim.x + threadIdx.x;
    int total = N_TOT_EDGES * H;
    if (t >= total) return;
    int h = t % H, e = t / H;
    int s, d;
    if (e < N_EDGES) { s = ei[e]; d = ei[N_EDGES + e]; } else { s = d = e - N_EDGES; }
    float v = as_[s*H + h] + ad_[d*H + h];
    v = v > 0.f ? v : 0.2f * v;
    atomicMaxFloat(&m[d*H + h], v);
}

__global__ void edge_sum(const int* __restrict__ ei, int H,
    const float* __restrict__ as_, const float* __restrict__ ad_,
    const float* __restrict__ m, float* __restrict__ z)
{
    int t = blockIdx.x * blockDim.x + threadIdx.x;
    int total = N_TOT_EDGES * H;
    if (t >= total) return;
    int h = t % H, e = t / H;
    int s, d;
    if (e < N_EDGES) { s = ei[e]; d = ei[N_EDGES + e]; } else { s = d = e - N_EDGES; }
    float v = as_[s*H + h] + ad_[d*H + h];
    v = v > 0.f ? v : 0.2f * v;
    atomicAdd(&z[d*H + h], expf(v - m[d*H + h]));
}

__global__ void edge_agg(const int* __restrict__ ei, int H,
    const float* __restrict__ as_, const float* __restrict__ ad_,
    const float* __restrict__ m, const float* __restrict__ hf,
    float* __restrict__ agg)
{
    int gw   = (blockIdx.x * blockDim.x + threadIdx.x) >> 5;
    int lane = threadIdx.x & 31;
    int total = N_TOT_EDGES * H;
    if (gw >= total) return;
    int h = gw % H, e = gw / H;
    int s, d;
    if (e < N_EDGES) { s = ei[e]; d = ei[N_EDGES + e]; } else { s = d = e - N_EDGES; }
    float v = as_[s*H + h] + ad_[d*H + h];
    v = v > 0.f ? v : 0.2f * v;
    float alpha = expf(v - m[d*H + h]);

    const float4 hx = *(const float4*)(hf + (((size_t)s*H + h) << 7) + lane*4);
    float* dstp = agg + (((size_t)d*H + h) << 7) + lane*4;
    asm volatile("red.global.add.v4.f32 [%0], {%1, %2, %3, %4};"
        :: "l"(dstp), "f"(hx.x*alpha), "f"(hx.y*alpha), "f"(hx.z*alpha), "f"(hx.w*alpha)
        : "memory");
}

// ------------------------- node epilogue ------------------------------------
__global__ void normalize_out(const float* __restrict__ agg,
    const float* __restrict__ z, const float* __restrict__ bias,
    float* __restrict__ out, int H, int relu)
{
    int idx = blockIdx.x * blockDim.x + threadIdx.x;
    int total = N_NODES * H * 128;
    if (idx >= total) return;
    int n  = idx / (H * 128);
    int hc = idx - n * H * 128;
    int head = hc >> 7;
    float v = agg[idx] / (z[n*H + head] + 1e-16f) + bias[hc];
    if (relu) v = fmaxf(v, 0.f);
    out[idx] = v;
}

// ------------------------- host orchestration -------------------------------
static void launch_gemm(const float* A, const float* W, float* C,
                        const float* bias, int M, int Nout, int K, int relu)
{
    dim3 grid(Nout / BN, (M + BM - 1) / BM);
    mma_gemm_nt<<<grid, 256, GEMM_SMEM_BYTES>>>(A, W, C, bias, M, Nout, K, relu);
}

static void run_gat_layer(const float* xin, int K, const float* Wl,
    const float* a_src, const float* a_dst, const float* b, int H,
    const int* ei, float* hf, float* agg, float* as_, float* ad_,
    float* m, float* z, float* out, int relu)
{
    int Nout = H * 128;
    launch_gemm(xin, Wl, hf, nullptr, N_NODES, Nout, K, 0);
    compute_alphas<<<N_NODES, dim3(32, H)>>>(hf, a_src, a_dst, as_, ad_, H);
    int nmz = N_NODES * H;
    init_mz<<<(nmz + 255)/256, 256>>>(m, z, nmz);
    cudaMemsetAsync(agg, 0, (size_t)N_NODES * Nout * sizeof(float));
    int tot = N_TOT_EDGES * H;
    edge_max<<<(tot + 255)/256, 256>>>(ei, H, as_, ad_, m);
    edge_sum<<<(tot + 255)/256, 256>>>(ei, H, as_, ad_, m, z);
    long long warps = (long long)tot * 32;
    edge_agg<<<(unsigned)((warps + 255)/256), 256>>>(ei, H, as_, ad_, m, hf, agg);
    normalize_out<<<(N_NODES*Nout + 255)/256, 256>>>(agg, z, b, out, H, relu);
}

extern "C" void kernel_launch(void* const* d_in, const int* in_sizes, int n_in,
                              void* d_out, int out_size)
{
    const float* x   = (const float*)d_in[0];
    const int*   ei  = (const int*)  d_in[1];
    const float* W0  = (const float*)d_in[2];
    const float* as0 = (const float*)d_in[3];
    const float* ad0 = (const float*)d_in[4];
    const float* b0  = (const float*)d_in[5];
    const float* W1  = (const float*)d_in[6];
    const float* as1 = (const float*)d_in[7];
    const float* ad1 = (const float*)d_in[8];
    const float* b1  = (const float*)d_in[9];
    const float* W2  = (const float*)d_in[10];
    const float* as2 = (const float*)d_in[11];
    const float* ad2 = (const float*)d_in[12];
    const float* b2  = (const float*)d_in[13];
    const float* Wv  = (const float*)d_in[14];
    const float* bv  = (const float*)d_in[15];
    const float* Wt  = (const float*)d_in[16];
    const float* bt  = (const float*)d_in[17];

    cudaFuncSetAttribute(mma_gemm_nt,
                         cudaFuncAttributeMaxDynamicSharedMemorySize,
                         GEMM_SMEM_BYTES);

    float *hf, *buf, *agg, *as_, *ad_, *m, *z;
    cudaGetSymbolAddress((void**)&hf,  g_hf);
    cudaGetSymbolAddress((void**)&buf, g_buf);
    cudaGetSymbolAddress((void**)&agg, g_agg);
    cudaGetSymbolAddress((void**)&as_, g_as);
    cudaGetSymbolAddress((void**)&ad_, g_ad);
    cudaGetSymbolAddress((void**)&m,   g_m);
    cudaGetSymbolAddress((void**)&z,   g_z);

    float* out = (float*)d_out;
    float* h2  = out;                               // [N,128]
    float* xv  = out + (size_t)N_NODES * 128;       // [N,128]
    float* xt  = out + (size_t)N_NODES * 256;       // [N,128]

    // layer 0: 512 -> 4x128, relu
    run_gat_layer(x,   512, W0, as0, ad0, b0, 4, ei, hf, agg, as_, ad_, m, z, buf, 1);
    // layer 1: 512 -> 4x128, relu
    run_gat_layer(buf, 512, W1, as1, ad1, b1, 4, ei, hf, agg, as_, ad_, m, z, buf, 1);
    // layer 2: 512 -> 1x128, no relu, writes h directly into d_out
    run_gat_layer(buf, 512, W2, as2, ad2, b2, 1, ei, hf, agg, as_, ad_, m, z, h2, 0);

    // output heads
    launch_gemm(h2, Wv, xv, bv, N_NODES, 128, 128, 1);
    launch_gemm(h2, Wt, xt, bt, N_NODES, 128, 128, 1);
}

// round 9
// speedup vs baseline: 2.2733x; 1.6698x over previous
#include <cuda_runtime.h>
#include <cstdint>

#define N_NODES 50000
#define N_EDGES 800000
#define N_TOT_EDGES (N_EDGES + N_NODES)   // self-loops appended

// ------------------------- scratch (device globals; no allocs allowed) ------
__device__ float g_hf [(size_t)N_NODES * 512];   // per-layer GEMM output h
__device__ float g_buf[(size_t)N_NODES * 512];   // layer activation ping-pong
__device__ float g_as [N_NODES * 4];
__device__ float g_ad [N_NODES * 4];
// CSR by destination (built once per launch; graph static within a call)
__device__ int   g_deg [N_NODES];
__device__ int   g_off [N_NODES + 1];
__device__ int   g_cur [N_NODES];
__device__ int   g_srcs[N_TOT_EDGES];            // src ids grouped by dst

// =============================================================================
// Tensor-core GEMM (unchanged from R8): C = A[M,K] * W[Nout,K]^T (+bias, relu)
// tf32 mma.sync m16n8k8, 2-term split, 2-stage cp.async double buffer.
// =============================================================================
#define BM 128
#define BN 128
#define BKC 32
#define SLD 36
#define GEMM_SMEM_BYTES (4 * 128 * SLD * 4)   // 72KB

__device__ __forceinline__ void mma8(float* d, const unsigned* a, const unsigned* b) {
    asm volatile(
        "mma.sync.aligned.m16n8k8.row.col.f32.tf32.tf32.f32 "
        "{%0,%1,%2,%3}, {%4,%5,%6,%7}, {%8,%9}, {%0,%1,%2,%3};"
        : "+f"(d[0]), "+f"(d[1]), "+f"(d[2]), "+f"(d[3])
        : "r"(a[0]), "r"(a[1]), "r"(a[2]), "r"(a[3]), "r"(b[0]), "r"(b[1]));
}

__device__ __forceinline__ void split_u(float v, unsigned& hi, unsigned& lo) {
    unsigned h = __float_as_uint(v) & 0xFFFFE000u;
    hi = h;
    lo = __float_as_uint(v - __uint_as_float(h));
}

__device__ __forceinline__ void cp_async16(uint32_t saddr, const void* gptr, int src_bytes) {
    asm volatile("cp.async.cg.shared.global [%0], [%1], 16, %2;"
        :: "r"(saddr), "l"(gptr), "r"(src_bytes));
}

__global__ __launch_bounds__(256) void mma_gemm_nt(
    const float* __restrict__ A, const float* __restrict__ W,
    float* __restrict__ C, const float* __restrict__ bias,
    int M, int Nout, int K, int relu)
{
    extern __shared__ float sm[];
    float* Asm[2] = { sm,               sm + 128 * SLD };
    float* Bsm[2] = { sm + 2*128*SLD,   sm + 3*128*SLD };
    const uint32_t smem_u32 = (uint32_t)__cvta_generic_to_shared(sm);

    const int tid  = threadIdx.x;
    const int lane = tid & 31;
    const int wid  = tid >> 5;
    const int g    = lane >> 2;
    const int t    = lane & 3;
    const int wm   = (wid & 1) * 64;
    const int wn   = (wid >> 1) * 32;
    const int mBase = blockIdx.y * BM;
    const int nBase = blockIdx.x * BN;

    const int lr = tid >> 3;
    const int lc = (tid & 7) * 4;

    float acc[4][4][4];
    #pragma unroll
    for (int mt = 0; mt < 4; mt++)
        #pragma unroll
        for (int nt = 0; nt < 4; nt++)
            #pragma unroll
            for (int i = 0; i < 4; i++) acc[mt][nt][i] = 0.0f;

    const int nk = K / BKC;

    auto issue_chunk = [&](int ck, int b) {
        const int k0 = ck * BKC;
        const uint32_t aOff = smem_u32 + (uint32_t)(b * 128 * SLD) * 4;
        const uint32_t bOff = smem_u32 + (uint32_t)((2 + b) * 128 * SLD) * 4;
        #pragma unroll
        for (int i = 0; i < 4; i++) {
            int r = lr + i * 32;
            int arow = mBase + r;
            int ok = arow < M;
            const float* ag = A + (size_t)(ok ? arow : 0) * K + k0 + lc;
            cp_async16(aOff + (uint32_t)(r * SLD + lc) * 4, ag, ok ? 16 : 0);
            const float* bg = W + (size_t)(nBase + r) * K + k0 + lc;
            cp_async16(bOff + (uint32_t)(r * SLD + lc) * 4, bg, 16);
        }
        asm volatile("cp.async.commit_group;");
    };

    issue_chunk(0, 0);

    for (int ck = 0; ck < nk; ck++) {
        const int cur = ck & 1;
        if (ck + 1 < nk) {
            issue_chunk(ck + 1, cur ^ 1);
            asm volatile("cp.async.wait_group 1;");
        } else {
            asm volatile("cp.async.wait_group 0;");
        }
        __syncthreads();

        const float* Ac = Asm[cur];
        const float* Bc = Bsm[cur];
        #pragma unroll
        for (int kk = 0; kk < 4; kk++) {
            const int kb = kk * 8;
            unsigned ah[4][4], al[4][4], bh[4][2], bl[4][2];
            #pragma unroll
            for (int mt = 0; mt < 4; mt++) {
                const float* p = Ac + (wm + mt * 16 + g) * SLD + kb + t;
                split_u(p[0],           ah[mt][0], al[mt][0]);
                split_u(p[8 * SLD],     ah[mt][1], al[mt][1]);
                split_u(p[4],           ah[mt][2], al[mt][2]);
                split_u(p[8 * SLD + 4], ah[mt][3], al[mt][3]);
            }
            #pragma unroll
            for (int nt = 0; nt < 4; nt++) {
                const float* p = Bc + (wn + nt * 8 + g) * SLD + kb + t;
                split_u(p[0], bh[nt][0], bl[nt][0]);
                split_u(p[4], bh[nt][1], bl[nt][1]);
            }
            #pragma unroll
            for (int mt = 0; mt < 4; mt++)
                #pragma unroll
                for (int nt = 0; nt < 4; nt++) {
                    mma8(acc[mt][nt], ah[mt], bh[nt]);
                    mma8(acc[mt][nt], al[mt], bh[nt]);
                    mma8(acc[mt][nt], ah[mt], bl[nt]);
                }
        }
        __syncthreads();
    }

    #pragma unroll
    for (int mt = 0; mt < 4; mt++) {
        int row0 = mBase + wm + mt * 16 + g;
        #pragma unroll
        for (int nt = 0; nt < 4; nt++) {
            int col = nBase + wn + nt * 8 + 2 * t;
            float b0 = bias ? bias[col]     : 0.f;
            float b1 = bias ? bias[col + 1] : 0.f;
            if (row0 < M) {
                float v0 = acc[mt][nt][0] + b0;
                float v1 = acc[mt][nt][1] + b1;
                if (relu) { v0 = fmaxf(v0, 0.f); v1 = fmaxf(v1, 0.f); }
                C[(size_t)row0 * Nout + col]     = v0;
                C[(size_t)row0 * Nout + col + 1] = v1;
            }
            if (row0 + 8 < M) {
                float v2 = acc[mt][nt][2] + b0;
                float v3 = acc[mt][nt][3] + b1;
                if (relu) { v2 = fmaxf(v2, 0.f); v3 = fmaxf(v3, 0.f); }
                C[(size_t)(row0 + 8) * Nout + col]     = v2;
                C[(size_t)(row0 + 8) * Nout + col + 1] = v3;
            }
        }
    }
}

// =============================================================================
// CSR build (once per launch): count -> scan -> scatter src ids grouped by dst
// =============================================================================
__global__ void csr_count(const int* __restrict__ ei, int* __restrict__ deg) {
    int e = blockIdx.x * blockDim.x + threadIdx.x;
    if (e >= N_TOT_EDGES) return;
    int d = (e < N_EDGES) ? ei[N_EDGES + e] : (e - N_EDGES);
    atomicAdd(&deg[d], 1);
}

// single-block exclusive scan of N_NODES ints; also copies offsets to cur
__global__ __launch_bounds__(1024) void csr_scan(
    const int* __restrict__ deg, int* __restrict__ off, int* __restrict__ cur)
{
    __shared__ int part[1024];
    const int tid = threadIdx.x;
    const int chunk = (N_NODES + 1023) / 1024;
    const int b = tid * chunk;
    const int e = min(b + chunk, N_NODES);
    int s = 0;
    for (int i = b; i < e; i++) s += deg[i];
    part[tid] = s;
    __syncthreads();
    for (int o = 1; o < 1024; o <<= 1) {
        int v = (tid >= o) ? part[tid - o] : 0;
        __syncthreads();
        part[tid] += v;
        __syncthreads();
    }
    int run = tid ? part[tid - 1] : 0;
    for (int i = b; i < e; i++) {
        off[i] = run; cur[i] = run;
        run += deg[i];
    }
    if (tid == 1023) off[N_NODES] = run;
}

__global__ void csr_scatter(const int* __restrict__ ei,
    int* __restrict__ cur, int* __restrict__ srcs)
{
    int e = blockIdx.x * blockDim.x + threadIdx.x;
    if (e >= N_TOT_EDGES) return;
    int s, d;
    if (e < N_EDGES) { s = ei[e]; d = ei[N_EDGES + e]; } else { s = d = e - N_EDGES; }
    int pos = atomicAdd(&cur[d], 1);
    srcs[pos] = s;
}

// ------------------------- per-node attention logits ------------------------
__global__ void compute_alphas(const float* __restrict__ hf,
    const float* __restrict__ a_src, const float* __restrict__ a_dst,
    float* __restrict__ as_, float* __restrict__ ad_, int H)
{
    int n    = blockIdx.x;
    int head = threadIdx.y;
    int lane = threadIdx.x;
    const float* hp = hf + ((size_t)n * H + head) * 128;
    float s1 = 0.f, s2 = 0.f;
    #pragma unroll
    for (int c = lane; c < 128; c += 32) {
        float hv = hp[c];
        s1 += hv * a_src[head*128 + c];
        s2 += hv * a_dst[head*128 + c];
    }
    #pragma unroll
    for (int o = 16; o > 0; o >>= 1) {
        s1 += __shfl_down_sync(0xffffffffu, s1, o);
        s2 += __shfl_down_sync(0xffffffffu, s2, o);
    }
    if (lane == 0) { as_[n*H + head] = s1; ad_[n*H + head] = s2; }
}

// =============================================================================
// Fused GAT aggregate: one warp per (dst node, head).
// Walks CSR in-edges; softmax WITHOUT max-subtraction (ratio-identical; logits
// are O(1) here so exp is fp32-safe). Accumulates z and the 128-ch weighted sum
// in registers; single store with 1/(z+eps), bias, relu. No atomics, no memset.
// =============================================================================
__global__ __launch_bounds__(256) void gat_aggregate(
    const int* __restrict__ off, const int* __restrict__ srcs,
    const float* __restrict__ as_, const float* __restrict__ ad_,
    const float* __restrict__ hf, const float* __restrict__ bias,
    float* __restrict__ out, int H, int relu)
{
    const int gw   = (blockIdx.x * blockDim.x + threadIdx.x) >> 5;
    const int lane = threadIdx.x & 31;
    if (gw >= N_NODES * H) return;
    const int n = gw / H;
    const int h = gw - n * H;

    const float adn = ad_[n*H + h];
    const int beg = off[n];
    const int end = off[n + 1];

    float4 acc = make_float4(0.f, 0.f, 0.f, 0.f);
    float zsum = 0.f;
    for (int i = beg; i < end; i++) {
        const int s = srcs[i];                       // uniform across warp
        float e = as_[s*H + h] + adn;                // broadcast load
        e = e > 0.f ? e : 0.2f * e;
        const float a = __expf(e);
        zsum += a;
        const float4 hx = *(const float4*)(hf + (((size_t)s*H + h) << 7) + lane*4);
        acc.x = fmaf(a, hx.x, acc.x);
        acc.y = fmaf(a, hx.y, acc.y);
        acc.z = fmaf(a, hx.z, acc.z);
        acc.w = fmaf(a, hx.w, acc.w);
    }
    const float inv = 1.0f / (zsum + 1e-16f);
    const int hc = h * 128 + lane * 4;
    float4 r;
    r.x = acc.x * inv + bias[hc + 0];
    r.y = acc.y * inv + bias[hc + 1];
    r.z = acc.z * inv + bias[hc + 2];
    r.w = acc.w * inv + bias[hc + 3];
    if (relu) {
        r.x = fmaxf(r.x, 0.f); r.y = fmaxf(r.y, 0.f);
        r.z = fmaxf(r.z, 0.f); r.w = fmaxf(r.w, 0.f);
    }
    *(float4*)(out + ((size_t)n * H + h) * 128 + lane * 4) = r;
}

// ------------------------- host orchestration -------------------------------
static void launch_gemm(const float* A, const float* W, float* C,
                        const float* bias, int M, int Nout, int K, int relu)
{
    dim3 grid(Nout / BN, (M + BM - 1) / BM);
    mma_gemm_nt<<<grid, 256, GEMM_SMEM_BYTES>>>(A, W, C, bias, M, Nout, K, relu);
}

static void run_gat_layer(const float* xin, int K, const float* Wl,
    const float* a_src, const float* a_dst, const float* b, int H,
    const int* off, const int* srcs,
    float* hf, float* as_, float* ad_, float* out, int relu)
{
    int Nout = H * 128;
    launch_gemm(xin, Wl, hf, nullptr, N_NODES, Nout, K, 0);
    compute_alphas<<<N_NODES, dim3(32, H)>>>(hf, a_src, a_dst, as_, ad_, H);
    int warps = N_NODES * H;
    gat_aggregate<<<(warps * 32 + 255) / 256, 256>>>(
        off, srcs, as_, ad_, hf, b, out, H, relu);
}

extern "C" void kernel_launch(void* const* d_in, const int* in_sizes, int n_in,
                              void* d_out, int out_size)
{
    const float* x   = (const float*)d_in[0];
    const int*   ei  = (const int*)  d_in[1];
    const float* W0  = (const float*)d_in[2];
    const float* as0 = (const float*)d_in[3];
    const float* ad0 = (const float*)d_in[4];
    const float* b0  = (const float*)d_in[5];
    const float* W1  = (const float*)d_in[6];
    const float* as1 = (const float*)d_in[7];
    const float* ad1 = (const float*)d_in[8];
    const float* b1  = (const float*)d_in[9];
    const float* W2  = (const float*)d_in[10];
    const float* as2 = (const float*)d_in[11];
    const float* ad2 = (const float*)d_in[12];
    const float* b2  = (const float*)d_in[13];
    const float* Wv  = (const float*)d_in[14];
    const float* bv  = (const float*)d_in[15];
    const float* Wt  = (const float*)d_in[16];
    const float* bt  = (const float*)d_in[17];

    cudaFuncSetAttribute(mma_gemm_nt,
                         cudaFuncAttributeMaxDynamicSharedMemorySize,
                         GEMM_SMEM_BYTES);

    float *hf, *buf, *as_, *ad_;
    int *deg, *off, *cur, *srcs;
    cudaGetSymbolAddress((void**)&hf,   g_hf);
    cudaGetSymbolAddress((void**)&buf,  g_buf);
    cudaGetSymbolAddress((void**)&as_,  g_as);
    cudaGetSymbolAddress((void**)&ad_,  g_ad);
    cudaGetSymbolAddress((void**)&deg,  g_deg);
    cudaGetSymbolAddress((void**)&off,  g_off);
    cudaGetSymbolAddress((void**)&cur,  g_cur);
    cudaGetSymbolAddress((void**)&srcs, g_srcs);

    float* out = (float*)d_out;
    float* h2  = out;                               // [N,128]
    float* xv  = out + (size_t)N_NODES * 128;       // [N,128]
    float* xt  = out + (size_t)N_NODES * 256;       // [N,128]

    // ---- CSR build (graph fixed within a call) ----
    cudaMemsetAsync(deg, 0, N_NODES * sizeof(int));
    csr_count  <<<(N_TOT_EDGES + 255)/256, 256>>>(ei, deg);
    csr_scan   <<<1, 1024>>>(deg, off, cur);
    csr_scatter<<<(N_TOT_EDGES + 255)/256, 256>>>(ei, cur, srcs);

    // layer 0: 512 -> 4x128, relu
    run_gat_layer(x,   512, W0, as0, ad0, b0, 4, off, srcs, hf, as_, ad_, buf, 1);
    // layer 1: 512 -> 4x128, relu
    run_gat_layer(buf, 512, W1, as1, ad1, b1, 4, off, srcs, hf, as_, ad_, buf, 1);
    // layer 2: 512 -> 1x128, no relu, writes h directly into d_out
    run_gat_layer(buf, 512, W2, as2, ad2, b2, 1, off, srcs, hf, as_, ad_, h2, 0);

    // output heads
    launch_gemm(h2, Wv, xv, bv, N_NODES, 128, 128, 1);
    launch_gemm(h2, Wt, xt, bt, N_NODES, 128, 128, 1);
}